// round 16
// baseline (speedup 1.0000x reference)
#include <cuda_runtime.h>
#include <cuda_fp16.h>
#include <math.h>
#include <stdint.h>

// Problem shape (fixed by the dataset)
#define BB 16
#define NN 8192
#define DD 128
#define HH 64
#define EE 64
#define EPS_LN 1e-5f

#define BLK1 64               // blocks per batch in pass 1
#define ROWS1 (NN / BLK1)     // 128 rows per pass-1 block
#define TILE 64               // rows per pass-3 tile
#define XSP 132               // padded X smem row stride (words)
#define NB3 296               // persistent k3 blocks (148 SMs x 2 CTAs)
#define NTILES_TOT (BB * NN / TILE)   // 2048

// ---------------- scratch (__device__ globals; no allocation allowed) -------
__device__ float  d_partial[BB][BLK1][DD];   // per-block col sums of (x-mu)*rstd
__device__ float2 d_stats[BB * NN];          // per-row {mu, rstd}
// G^T as fp16 in m16n8k16 fragment-major order:
// uint4 #(ks*4+j) per lane: {b0(tile 2j), b1(tile 2j), b0(tile 2j+1), b1(tile 2j+1)}
#define GFH_WORDS (8 * 4 * 32 * 4)           // 4096 words = 16KB
__device__ __align__(16) uint32_t d_Gf[BB][GFH_WORDS];
__device__ float  d_u[BB][EE];               // u = (ln_w@Wr ⊙ lm) @ Wo
__device__ float  d_h[BB][EE];               // h = (ln_b@Wr ⊙ lm) @ Wo + c

__device__ __forceinline__ uint32_t smem_u32(const void* p) {
    uint32_t a;
    asm("{ .reg .u64 t; cvta.to.shared.u64 t, %1; cvt.u32.u64 %0, t; }" : "=r"(a) : "l"(p));
    return a;
}
__device__ __forceinline__ void cp16(uint32_t dst, const void* src) {
    asm volatile("cp.async.cg.shared.global [%0], [%1], 16;"
                 :: "r"(dst), "l"(src) : "memory");
}
__device__ __forceinline__ uint32_t packh2(float lo, float hi) {
    __half2 h = __floats2half2_rn(lo, hi);
    return *(uint32_t*)&h;
}
__device__ __forceinline__ void mma_f16(float* c, const uint32_t* a,
                                        uint32_t b0, uint32_t b1) {
    asm volatile(
        "mma.sync.aligned.m16n8k16.row.col.f32.f16.f16.f32 "
        "{%0,%1,%2,%3}, {%4,%5,%6,%7}, {%8,%9}, {%0,%1,%2,%3};"
        : "+f"(c[0]), "+f"(c[1]), "+f"(c[2]), "+f"(c[3])
        : "r"(a[0]), "r"(a[1]), "r"(a[2]), "r"(a[3]), "r"(b0), "r"(b1));
}

// ============================ Pass 1: row stats + column sums ===============
// (exact R11 configuration — measured at its streaming floor)
__global__ void k1_stats(const float* __restrict__ x) {
    int b    = blockIdx.y;
    int w    = threadIdx.x >> 5;
    int lane = threadIdx.x & 31;
    int rp   = lane >> 3;
    int c    = lane & 7;
    int rowbase = blockIdx.x * ROWS1 + w * (ROWS1 / 8);

    const float4* xb = (const float4*)(x + (size_t)b * NN * DD);

    float4 acc[4];
    #pragma unroll
    for (int j = 0; j < 4; j++) acc[j] = make_float4(0.f, 0.f, 0.f, 0.f);

    #pragma unroll
    for (int it = 0; it < 4; it++) {
        int row = rowbase + it * 4 + rp;
        float4 v[4];
        #pragma unroll
        for (int j = 0; j < 4; j++)
            v[j] = xb[row * (DD / 4) + (c + 8 * j)];
        float s = 0.f, q = 0.f;
        #pragma unroll
        for (int j = 0; j < 4; j++) {
            s += v[j].x + v[j].y + v[j].z + v[j].w;
            q += v[j].x * v[j].x + v[j].y * v[j].y + v[j].z * v[j].z + v[j].w * v[j].w;
        }
        #pragma unroll
        for (int o = 4; o > 0; o >>= 1) {
            s += __shfl_xor_sync(0xffffffffu, s, o);
            q += __shfl_xor_sync(0xffffffffu, q, o);
        }
        float mu   = s * (1.0f / DD);
        float rstd = rsqrtf(q * (1.0f / DD) - mu * mu + EPS_LN);
        if (c == 0) d_stats[b * NN + row] = make_float2(mu, rstd);
        #pragma unroll
        for (int j = 0; j < 4; j++) {
            acc[j].x += (v[j].x - mu) * rstd;
            acc[j].y += (v[j].y - mu) * rstd;
            acc[j].z += (v[j].z - mu) * rstd;
            acc[j].w += (v[j].w - mu) * rstd;
        }
    }

    __shared__ float sred[32][DD];
    {
        float4* dst = (float4*)sred[w * 4 + rp];
        #pragma unroll
        for (int j = 0; j < 4; j++) dst[c + 8 * j] = acc[j];
    }
    __syncthreads();
    if (threadIdx.x < DD) {
        float s = 0.f;
        #pragma unroll
        for (int k = 0; k < 32; k++) s += sred[k][threadIdx.x];
        d_partial[b][blockIdx.x][threadIdx.x] = s;
    }
}

// ============================ Pass 2: fold (one kernel, 128 blocks) ==========
__global__ void __launch_bounds__(256) k2_fold(
    const float* __restrict__ ln_w, const float* __restrict__ ln_b,
    const float* __restrict__ Wl,   const float* __restrict__ bl,
    const float* __restrict__ Wr,   const float* __restrict__ br,
    const float* __restrict__ Wo,   const float* __restrict__ bo) {
    __shared__ float sxa[2][DD];
    __shared__ float sx[DD];
    __shared__ float sr4[4][HH];
    __shared__ float slm[HH];
    __shared__ float sP[HH * EE];
    __shared__ float sWr[16 * HH];
    __shared__ float swv4[4][HH], sbv4[4][HH];

    int b = blockIdx.y, bx = blockIdx.x, tid = threadIdx.x;
    int d0 = bx * 16;

    {
        int col = tid & 127, hf = tid >> 7;
        float s = 0.f;
        #pragma unroll 8
        for (int p = hf * 32; p < hf * 32 + 32; p++) s += d_partial[b][p][col];
        sxa[hf][col] = s;
    }
    #pragma unroll
    for (int i = tid; i < 16 * HH; i += 256)
        sWr[i] = Wr[(d0 + (i >> 6)) * HH + (i & 63)];
    __syncthreads();
    if (tid < DD)
        sx[tid] = ln_w[tid] * ((sxa[0][tid] + sxa[1][tid]) * (1.0f / NN)) + ln_b[tid];
    __syncthreads();

    {
        int h = tid & 63, q = tid >> 6;
        float a = 0.f;
        #pragma unroll 8
        for (int d = q * 32; d < q * 32 + 32; d++) a += sx[d] * Wl[d * HH + h];
        sr4[q][h] = a;
    }
    __syncthreads();
    if (tid < HH)
        slm[tid] = bl[tid] + sr4[0][tid] + sr4[1][tid] + sr4[2][tid] + sr4[3][tid];
    __syncthreads();

    #pragma unroll
    for (int i = tid; i < HH * EE; i += 256) sP[i] = slm[i >> 6] * Wo[i];
    __syncthreads();

    // G rows -> fp16 fragment-major into d_Gf (m16n8k16 B fragments)
    {
        int d_l = tid >> 4, e0 = (tid & 15) * 4;
        float a0 = 0.f, a1 = 0.f, a2 = 0.f, a3 = 0.f;
        #pragma unroll 8
        for (int h = 0; h < HH; h++) {
            float wv = sWr[d_l * HH + h];
            const float* p = &sP[h * EE + e0];
            a0 += wv * p[0]; a1 += wv * p[1]; a2 += wv * p[2]; a3 += wv * p[3];
        }
        int d = d0 + d_l;
        float lw = ln_w[d];
        float gv[4] = { lw * a0, lw * a1, lw * a2, lw * a3 };
        int ks   = d >> 4;          // k16 step
        int kk   = d & 15;          // k within step
        int tq   = (kk >> 1) & 3;   // fragment t
        int half = kk & 1;          // lo/hi half of the b32
        int hi8  = kk >> 3;         // b0 (k<8) or b1 (k>=8)
        __half* gh = (__half*)d_Gf[b];
        #pragma unroll
        for (int j = 0; j < 4; j++) {
            int e = e0 + j;
            int g = e & 7, nt = e >> 3, jj = nt >> 1;
            int comp = (nt & 1) * 2 + hi8;
            int laneix = g * 4 + tq;
            int word = ((ks * 4 + jj) * 32 + laneix) * 4 + comp;
            gh[word * 2 + half] = __float2half_rn(gv[j]);
        }
    }

    if (bx == 0) {
        {
            int h = tid & 63, q = tid >> 6;
            float aw = 0.f, ab = 0.f;
            #pragma unroll 8
            for (int d = q * 32; d < q * 32 + 32; d++) {
                float wr = Wr[d * HH + h];
                aw += ln_w[d] * wr;
                ab += ln_b[d] * wr;
            }
            swv4[q][h] = aw; sbv4[q][h] = ab;
        }
        __syncthreads();
        if (tid < EE) {
            int e = tid;
            float su = 0.f, sh = 0.f, sc = bo[e];
            #pragma unroll 8
            for (int h = 0; h < HH; h++) {
                float p  = sP[h * EE + e];
                float wv = swv4[0][h] + swv4[1][h] + swv4[2][h] + swv4[3][h];
                float bv = sbv4[0][h] + sbv4[1][h] + sbv4[2][h] + sbv4[3][h];
                su += wv * p;
                sh += bv * p;
                sc += br[h] * p;
            }
            d_u[b][e] = su;
            d_h[b][e] = sh + sc;
        }
    }
}

// ============================ Pass 3: persistent fp16 GEMM ===================
// 296 blocks (2 CTAs/SM, one wave). Block owns a contiguous chunk of 6-7
// 64-row tiles; Gf/u/h staged per batch (rare restage), X double-buffered.
#define K3_SMEM_WORDS (GFH_WORDS + 2 * TILE * XSP + EE + EE)

__global__ void __launch_bounds__(128, 2) k3_mma(const float* __restrict__ x,
                                                 float* __restrict__ out) {
    extern __shared__ uint32_t sm[];
    uint32_t* Gf = sm;                         // [8][4][32] uint4 fragment-major
    uint32_t* Xb = Gf + GFH_WORDS;             // [2][TILE][XSP] raw fp32 bits
    float*    su = (float*)(Xb + 2 * TILE * XSP);
    float*    sh = su + EE;

    int bid  = blockIdx.x;
    int tid  = threadIdx.x;
    int w    = tid >> 5, lane = tid & 31;
    int g    = lane >> 2, t = lane & 3;

    int base = 6 * bid + (bid < 272 ? bid : 272);   // 272 blocks x7 + 24 x6
    int cnt  = 6 + (bid < 272 ? 1 : 0);

    int curb = base >> 7;   // batch of first tile

    // ---- initial stage: Gf(curb) + u/h + X(tile base) -> buf 0 ----
    {
        const char* gsrc = (const char*)d_Gf[curb];
        #pragma unroll
        for (int i = 0; i < 8; i++) {
            int fid = tid + i * 128;
            cp16(smem_u32(&Gf[fid * 4]), gsrc + (size_t)fid * 16);
        }
        if (tid < EE) { su[tid] = d_u[curb][tid]; sh[tid] = d_h[curb][tid]; }
        int row0 = (base & 127) * TILE;
        const char* xsrc = (const char*)(x + ((size_t)curb * NN + row0) * DD);
        #pragma unroll
        for (int i = 0; i < 16; i++) {
            int fid = tid + i * 128;
            int r = fid >> 5, cq = fid & 31;
            cp16(smem_u32(&Xb[r * XSP + 4 * cq]), xsrc + (size_t)fid * 16);
        }
        asm volatile("cp.async.commit_group;" ::: "memory");
    }

    int buf = 0;
    for (int j = 0; j < cnt; j++) {
        int tile = base + j;
        int b    = tile >> 7;
        int row0 = (tile & 127) * TILE;
        int rl   = w * 16 + g;

        // prefetch this tile's row stats into registers (hidden under wait)
        float2 st0 = d_stats[b * NN + row0 + rl];
        float2 st8 = d_stats[b * NN + row0 + rl + 8];

        // prefetch next X into the other buffer
        bool have_next = (j + 1 < cnt);
        if (have_next) {
            int ntile = tile + 1;
            int nb = ntile >> 7;
            int nrow0 = (ntile & 127) * TILE;
            const char* xsrc = (const char*)(x + ((size_t)nb * NN + nrow0) * DD);
            uint32_t* dst = Xb + (buf ^ 1) * TILE * XSP;
            #pragma unroll
            for (int i = 0; i < 16; i++) {
                int fid = tid + i * 128;
                int r = fid >> 5, cq = fid & 31;
                cp16(smem_u32(&dst[r * XSP + 4 * cq]), xsrc + (size_t)fid * 16);
            }
            asm volatile("cp.async.commit_group;" ::: "memory");
        }

        if (b != curb) {
            // rare: batch boundary inside chunk — drain, restage Gf/u/h
            asm volatile("cp.async.wait_group 0;" ::: "memory");
            __syncthreads();
            const char* gsrc = (const char*)d_Gf[b];
            #pragma unroll
            for (int i = 0; i < 8; i++) {
                int fid = tid + i * 128;
                cp16(smem_u32(&Gf[fid * 4]), gsrc + (size_t)fid * 16);
            }
            if (tid < EE) { su[tid] = d_u[b][tid]; sh[tid] = d_h[b][tid]; }
            asm volatile("cp.async.commit_group;" ::: "memory");
            asm volatile("cp.async.wait_group 0;" ::: "memory");
            curb = b;
        } else if (have_next) {
            asm volatile("cp.async.wait_group 1;" ::: "memory");
        } else {
            asm volatile("cp.async.wait_group 0;" ::: "memory");
        }
        __syncthreads();

        const uint32_t* Xs = Xb + buf * TILE * XSP;

        // ---- mainloop: 8 k16-steps; A = 4 LDS.64 + 4 packs, B = 4 LDS.128 --
        float acc[8][4];
        #pragma unroll
        for (int nt = 0; nt < 8; nt++)
            #pragma unroll
            for (int jj = 0; jj < 4; jj++) acc[nt][jj] = 0.f;

        const float* xr0 = (const float*)&Xs[rl * XSP + 2 * t];
        const float* xr8 = (const float*)&Xs[(rl + 8) * XSP + 2 * t];

        #pragma unroll
        for (int ks = 0; ks < 8; ks++) {
            int k0 = ks * 16;
            float2 v0 = *(const float2*)(xr0 + k0);
            float2 v1 = *(const float2*)(xr8 + k0);
            float2 v2 = *(const float2*)(xr0 + k0 + 8);
            float2 v3 = *(const float2*)(xr8 + k0 + 8);
            uint32_t a[4];
            a[0] = packh2(v0.x, v0.y);
            a[1] = packh2(v1.x, v1.y);
            a[2] = packh2(v2.x, v2.y);
            a[3] = packh2(v3.x, v3.y);

            const uint4* gfk = (const uint4*)&Gf[(ks * 4) * 32 * 4];
            #pragma unroll
            for (int jj = 0; jj < 4; jj++) {
                uint4 q = gfk[jj * 32 + lane];
                mma_f16(acc[2 * jj + 0], a, q.x, q.y);
                mma_f16(acc[2 * jj + 1], a, q.z, q.w);
            }
        }

        // ---- epilogue: out = rstd*(acc - mu*u) + h ----
        {
            size_t ob0 = ((size_t)b * NN + row0 + rl) * EE;
            size_t ob8 = ob0 + 8 * EE;
            #pragma unroll
            for (int nt = 0; nt < 8; nt++) {
                int c = nt * 8 + t * 2;
                float2 uv = *(float2*)&su[c];
                float2 hv = *(float2*)&sh[c];
                float2 o0, o8;
                o0.x = st0.y * (acc[nt][0] - st0.x * uv.x) + hv.x;
                o0.y = st0.y * (acc[nt][1] - st0.x * uv.y) + hv.y;
                o8.x = st8.y * (acc[nt][2] - st8.x * uv.x) + hv.x;
                o8.y = st8.y * (acc[nt][3] - st8.x * uv.y) + hv.y;
                *(float2*)&out[ob0 + c] = o0;
                *(float2*)&out[ob8 + c] = o8;
            }
        }
        __syncthreads();   // all reads of this X buffer done before reuse
        buf ^= 1;
    }
}

// ============================ launch =========================================
extern "C" void kernel_launch(void* const* d_in, const int* in_sizes, int n_in,
                              void* d_out, int out_size) {
    const float* x    = (const float*)d_in[0];
    const float* ln_w = (const float*)d_in[1];
    const float* ln_b = (const float*)d_in[2];
    const float* Wl   = (const float*)d_in[3];
    const float* bl   = (const float*)d_in[4];
    const float* Wr   = (const float*)d_in[5];
    const float* br   = (const float*)d_in[6];
    const float* Wo   = (const float*)d_in[7];
    const float* bo   = (const float*)d_in[8];
    float* out = (float*)d_out;

    const int k3_smem = K3_SMEM_WORDS * (int)sizeof(uint32_t);
    cudaFuncSetAttribute(k3_mma, cudaFuncAttributeMaxDynamicSharedMemorySize, k3_smem);

    k1_stats<<<dim3(BLK1, BB), 256>>>(x);
    k2_fold<<<dim3(8, BB), 256>>>(ln_w, ln_b, Wl, bl, Wr, br, Wo, bo);
    k3_mma<<<NB3, 128, k3_smem>>>(x, out);
}

// round 17
// speedup vs baseline: 1.0417x; 1.0417x over previous
#include <cuda_runtime.h>
#include <cuda_fp16.h>
#include <math.h>
#include <stdint.h>

// Problem shape (fixed by the dataset)
#define BB 16
#define NN 8192
#define DD 128
#define HH 64
#define EE 64
#define EPS_LN 1e-5f

#define BLK1 64               // blocks per batch in pass 1
#define ROWS1 (NN / BLK1)     // 128 rows per pass-1 block
#define TILE 64               // rows per pass-3 block
#define XHW 68                // X fp16x2 smem row stride in words (≡4 mod 32)

// ---------------- scratch (__device__ globals; no allocation allowed) -------
__device__ float  d_partial[BB][BLK1][DD];   // per-block col sums of (x-mu)*rstd
__device__ float2 d_stats[BB * NN];          // per-row {mu, rstd}
// G^T as fp16 in m16n8k16 fragment-major order:
// uint4 #(ks*4+j) per lane: {b0(tile 2j), b1(tile 2j), b0(tile 2j+1), b1(tile 2j+1)}
#define GFH_WORDS (8 * 4 * 32 * 4)           // 4096 words = 16KB
__device__ __align__(16) uint32_t d_Gf[BB][GFH_WORDS];
__device__ float  d_u[BB][EE];               // u = (ln_w@Wr ⊙ lm) @ Wo
__device__ float  d_h[BB][EE];               // h = (ln_b@Wr ⊙ lm) @ Wo + c

__device__ __forceinline__ uint32_t smem_u32(const void* p) {
    uint32_t a;
    asm("{ .reg .u64 t; cvta.to.shared.u64 t, %1; cvt.u32.u64 %0, t; }" : "=r"(a) : "l"(p));
    return a;
}
__device__ __forceinline__ void cp16(uint32_t dst, const void* src) {
    asm volatile("cp.async.cg.shared.global [%0], [%1], 16;"
                 :: "r"(dst), "l"(src) : "memory");
}
__device__ __forceinline__ uint32_t packh2(float lo, float hi) {
    __half2 h = __floats2half2_rn(lo, hi);
    return *(uint32_t*)&h;
}
__device__ __forceinline__ void mma_f16(float* c, const uint32_t* a,
                                        uint32_t b0, uint32_t b1) {
    asm volatile(
        "mma.sync.aligned.m16n8k16.row.col.f32.f16.f16.f32 "
        "{%0,%1,%2,%3}, {%4,%5,%6,%7}, {%8,%9}, {%0,%1,%2,%3};"
        : "+f"(c[0]), "+f"(c[1]), "+f"(c[2]), "+f"(c[3])
        : "r"(a[0]), "r"(a[1]), "r"(a[2]), "r"(a[3]), "r"(b0), "r"(b1));
}

// ============================ Pass 1: row stats + column sums ===============
// (exact R11 configuration — measured at its streaming floor)
__global__ void k1_stats(const float* __restrict__ x) {
    int b    = blockIdx.y;
    int w    = threadIdx.x >> 5;
    int lane = threadIdx.x & 31;
    int rp   = lane >> 3;
    int c    = lane & 7;
    int rowbase = blockIdx.x * ROWS1 + w * (ROWS1 / 8);

    const float4* xb = (const float4*)(x + (size_t)b * NN * DD);

    float4 acc[4];
    #pragma unroll
    for (int j = 0; j < 4; j++) acc[j] = make_float4(0.f, 0.f, 0.f, 0.f);

    #pragma unroll
    for (int it = 0; it < 4; it++) {
        int row = rowbase + it * 4 + rp;
        float4 v[4];
        #pragma unroll
        for (int j = 0; j < 4; j++)
            v[j] = xb[row * (DD / 4) + (c + 8 * j)];
        float s = 0.f, q = 0.f;
        #pragma unroll
        for (int j = 0; j < 4; j++) {
            s += v[j].x + v[j].y + v[j].z + v[j].w;
            q += v[j].x * v[j].x + v[j].y * v[j].y + v[j].z * v[j].z + v[j].w * v[j].w;
        }
        #pragma unroll
        for (int o = 4; o > 0; o >>= 1) {
            s += __shfl_xor_sync(0xffffffffu, s, o);
            q += __shfl_xor_sync(0xffffffffu, q, o);
        }
        float mu   = s * (1.0f / DD);
        float rstd = rsqrtf(q * (1.0f / DD) - mu * mu + EPS_LN);
        if (c == 0) d_stats[b * NN + row] = make_float2(mu, rstd);
        #pragma unroll
        for (int j = 0; j < 4; j++) {
            acc[j].x += (v[j].x - mu) * rstd;
            acc[j].y += (v[j].y - mu) * rstd;
            acc[j].z += (v[j].z - mu) * rstd;
            acc[j].w += (v[j].w - mu) * rstd;
        }
    }

    __shared__ float sred[32][DD];
    {
        float4* dst = (float4*)sred[w * 4 + rp];
        #pragma unroll
        for (int j = 0; j < 4; j++) dst[c + 8 * j] = acc[j];
    }
    __syncthreads();
    if (threadIdx.x < DD) {
        float s = 0.f;
        #pragma unroll
        for (int k = 0; k < 32; k++) s += sred[k][threadIdx.x];
        d_partial[b][blockIdx.x][threadIdx.x] = s;
    }
}

// ============================ Pass 2: fold (one kernel, 128 blocks) ==========
__global__ void __launch_bounds__(256) k2_fold(
    const float* __restrict__ ln_w, const float* __restrict__ ln_b,
    const float* __restrict__ Wl,   const float* __restrict__ bl,
    const float* __restrict__ Wr,   const float* __restrict__ br,
    const float* __restrict__ Wo,   const float* __restrict__ bo) {
    __shared__ float sxa[2][DD];
    __shared__ float sx[DD];
    __shared__ float sr4[4][HH];
    __shared__ float slm[HH];
    __shared__ float sP[HH * EE];
    __shared__ float sWr[16 * HH];
    __shared__ float swv4[4][HH], sbv4[4][HH];

    int b = blockIdx.y, bx = blockIdx.x, tid = threadIdx.x;
    int d0 = bx * 16;

    {
        int col = tid & 127, hf = tid >> 7;
        float s = 0.f;
        #pragma unroll 8
        for (int p = hf * 32; p < hf * 32 + 32; p++) s += d_partial[b][p][col];
        sxa[hf][col] = s;
    }
    #pragma unroll
    for (int i = tid; i < 16 * HH; i += 256)
        sWr[i] = Wr[(d0 + (i >> 6)) * HH + (i & 63)];
    __syncthreads();
    if (tid < DD)
        sx[tid] = ln_w[tid] * ((sxa[0][tid] + sxa[1][tid]) * (1.0f / NN)) + ln_b[tid];
    __syncthreads();

    {
        int h = tid & 63, q = tid >> 6;
        float a = 0.f;
        #pragma unroll 8
        for (int d = q * 32; d < q * 32 + 32; d++) a += sx[d] * Wl[d * HH + h];
        sr4[q][h] = a;
    }
    __syncthreads();
    if (tid < HH)
        slm[tid] = bl[tid] + sr4[0][tid] + sr4[1][tid] + sr4[2][tid] + sr4[3][tid];
    __syncthreads();

    #pragma unroll
    for (int i = tid; i < HH * EE; i += 256) sP[i] = slm[i >> 6] * Wo[i];
    __syncthreads();

    // G rows -> fp16 fragment-major into d_Gf (m16n8k16 B fragments)
    {
        int d_l = tid >> 4, e0 = (tid & 15) * 4;
        float a0 = 0.f, a1 = 0.f, a2 = 0.f, a3 = 0.f;
        #pragma unroll 8
        for (int h = 0; h < HH; h++) {
            float wv = sWr[d_l * HH + h];
            const float* p = &sP[h * EE + e0];
            a0 += wv * p[0]; a1 += wv * p[1]; a2 += wv * p[2]; a3 += wv * p[3];
        }
        int d = d0 + d_l;
        float lw = ln_w[d];
        float gv[4] = { lw * a0, lw * a1, lw * a2, lw * a3 };
        int ks   = d >> 4;          // k16 step
        int kk   = d & 15;          // k within step
        int tq   = (kk >> 1) & 3;   // fragment t
        int half = kk & 1;          // lo/hi half of the b32
        int hi8  = kk >> 3;         // b0 (k<8) or b1 (k>=8)
        __half* gh = (__half*)d_Gf[b];
        #pragma unroll
        for (int j = 0; j < 4; j++) {
            int e = e0 + j;
            int g = e & 7, nt = e >> 3, jj = nt >> 1;
            int comp = (nt & 1) * 2 + hi8;
            int laneix = g * 4 + tq;
            int word = ((ks * 4 + jj) * 32 + laneix) * 4 + comp;
            gh[word * 2 + half] = __float2half_rn(gv[j]);
        }
    }

    if (bx == 0) {
        {
            int h = tid & 63, q = tid >> 6;
            float aw = 0.f, ab = 0.f;
            #pragma unroll 8
            for (int d = q * 32; d < q * 32 + 32; d++) {
                float wr = Wr[d * HH + h];
                aw += ln_w[d] * wr;
                ab += ln_b[d] * wr;
            }
            swv4[q][h] = aw; sbv4[q][h] = ab;
        }
        __syncthreads();
        if (tid < EE) {
            int e = tid;
            float su = 0.f, sh = 0.f, sc = bo[e];
            #pragma unroll 8
            for (int h = 0; h < HH; h++) {
                float p  = sP[h * EE + e];
                float wv = swv4[0][h] + swv4[1][h] + swv4[2][h] + swv4[3][h];
                float bv = sbv4[0][h] + sbv4[1][h] + sbv4[2][h] + sbv4[3][h];
                su += wv * p;
                sh += bv * p;
                sc += br[h] * p;
            }
            d_u[b][e] = su;
            d_h[b][e] = sh + sc;
        }
    }
}

// ============================ Pass 3: mma.sync fp16 GEMM =====================
// D[64,64] = X_tile[64,128] @ G[128,64] via m16n8k16 (8 k-steps, 64 HMMA/warp).
// X stored in smem as fp16x2 (stride 68 words: banks = 4g+t, conflict-free).
// smem ~34KB -> 6 CTAs/SM (24 warps). Gf via cp.async; X via LDG->pack->STS.
#define K3_SMEM_WORDS (GFH_WORDS + TILE * XHW + EE + EE + 2 * TILE)

__global__ void __launch_bounds__(128, 6) k3_mma(const float* __restrict__ x,
                                                 float* __restrict__ out) {
    extern __shared__ uint32_t sm[];
    uint32_t* Gf  = sm;                        // [8][4][32] uint4 fragment-major
    uint32_t* Xh  = Gf + GFH_WORDS;            // [TILE][XHW] fp16x2 words
    float*    su  = (float*)(Xh + TILE * XHW); // [EE]
    float*    sh  = su + EE;                   // [EE]
    float2*   sst = (float2*)(sh + EE);        // [TILE]

    int b    = blockIdx.y;
    int tid  = threadIdx.x;
    int w    = tid >> 5, lane = tid & 31;
    int g    = lane >> 2, t = lane & 3;
    int row0 = blockIdx.x * TILE;

    // ---- stage Gf via cp.async (8 chunks/thread) ----
    {
        const char* gsrc = (const char*)d_Gf[b];
        #pragma unroll
        for (int i = 0; i < 8; i++) {
            int fid = tid + i * 128;           // 1024 16B chunks
            cp16(smem_u32(&Gf[fid * 4]), gsrc + (size_t)fid * 16);
        }
        asm volatile("cp.async.commit_group;" ::: "memory");
    }
    // ---- stage X: LDG.128 -> fp16 pack -> STS.64 (16 chunks/thread) ----
    {
        const float4* xb = (const float4*)(x + ((size_t)b * NN + row0) * DD);
        #pragma unroll
        for (int i = 0; i < 16; i++) {
            int fid = tid + i * 128;           // 2048 float4 chunks
            int r = fid >> 5, cq = fid & 31;
            float4 v = xb[fid];
            uint2 p = make_uint2(packh2(v.x, v.y), packh2(v.z, v.w));
            *(uint2*)&Xh[r * XHW + 2 * cq] = p;
        }
    }
    if (tid < EE) { su[tid] = d_u[b][tid]; sh[tid] = d_h[b][tid]; }
    if (tid < TILE) sst[tid] = d_stats[b * NN + row0 + tid];
    asm volatile("cp.async.wait_group 0;" ::: "memory");
    __syncthreads();

    // ---- mainloop: 8 k16-steps; A = 4 LDS.32 (pre-packed), B = 4 LDS.128 ----
    float acc[8][4];
    #pragma unroll
    for (int nt = 0; nt < 8; nt++)
        #pragma unroll
        for (int j = 0; j < 4; j++) acc[nt][j] = 0.f;

    int rl = w * 16 + g;
    const uint32_t* xr0 = &Xh[rl * XHW + t];
    const uint32_t* xr8 = &Xh[(rl + 8) * XHW + t];

    #pragma unroll
    for (int ks = 0; ks < 8; ks++) {
        int k0 = ks * 8;
        uint32_t a[4];
        a[0] = xr0[k0];
        a[1] = xr8[k0];
        a[2] = xr0[k0 + 4];
        a[3] = xr8[k0 + 4];

        const uint4* gfk = (const uint4*)&Gf[(ks * 4) * 32 * 4];
        #pragma unroll
        for (int j = 0; j < 4; j++) {
            uint4 q = gfk[j * 32 + lane];
            mma_f16(acc[2 * j + 0], a, q.x, q.y);
            mma_f16(acc[2 * j + 1], a, q.z, q.w);
        }
    }

    // ---- epilogue: out = rstd*(acc - mu*u) + h ----
    {
        float2 st0 = sst[rl];
        float2 st8 = sst[rl + 8];
        size_t ob0 = ((size_t)b * NN + row0 + rl) * EE;
        size_t ob8 = ob0 + 8 * EE;
        #pragma unroll
        for (int nt = 0; nt < 8; nt++) {
            int c = nt * 8 + t * 2;
            float2 uv = *(float2*)&su[c];
            float2 hv = *(float2*)&sh[c];
            float2 o0, o8;
            o0.x = st0.y * (acc[nt][0] - st0.x * uv.x) + hv.x;
            o0.y = st0.y * (acc[nt][1] - st0.x * uv.y) + hv.y;
            o8.x = st8.y * (acc[nt][2] - st8.x * uv.x) + hv.x;
            o8.y = st8.y * (acc[nt][3] - st8.x * uv.y) + hv.y;
            *(float2*)&out[ob0 + c] = o0;
            *(float2*)&out[ob8 + c] = o8;
        }
    }
}

// ============================ launch =========================================
extern "C" void kernel_launch(void* const* d_in, const int* in_sizes, int n_in,
                              void* d_out, int out_size) {
    const float* x    = (const float*)d_in[0];
    const float* ln_w = (const float*)d_in[1];
    const float* ln_b = (const float*)d_in[2];
    const float* Wl   = (const float*)d_in[3];
    const float* bl   = (const float*)d_in[4];
    const float* Wr   = (const float*)d_in[5];
    const float* br   = (const float*)d_in[6];
    const float* Wo   = (const float*)d_in[7];
    const float* bo   = (const float*)d_in[8];
    float* out = (float*)d_out;

    const int k3_smem = K3_SMEM_WORDS * (int)sizeof(uint32_t);
    cudaFuncSetAttribute(k3_mma, cudaFuncAttributeMaxDynamicSharedMemorySize, k3_smem);

    k1_stats<<<dim3(BLK1, BB), 256>>>(x);
    k2_fold<<<dim3(8, BB), 256>>>(ln_w, ln_b, Wl, bl, Wr, br, Wo, bo);
    k3_mma<<<dim3(NN / TILE, BB), 128, k3_smem>>>(x, out);
}